// round 11
// baseline (speedup 1.0000x reference)
#include <cuda_runtime.h>
#include <cuda_bf16.h>

// ---------------------------------------------------------------------------
// Separable RBF network (centers = 20x5x20 meshgrid, uniform beta):
//   exp(-beta|x-c|^2) = u_i(x0) * v_j(x1) * w_k(x2)
//   out = ( sum_ijk W[i,j,k] u_i v_j w_k ) / ( (sum u)(sum v)(sum w) )
// Tensor-core formulation: per CTA-tile of 128 points,
//   Q[ij, n] = sum_k Wmat[ij, k] * w_k(n)        <- mma.sync tf32 GEMM
//   num(n)   = sum_i U_i(n) sum_j V_j(n) Q[i*5+j, n]   <- 125 scalar FMAs
// 3xTF32 (hi/lo split, 3 accumulating MMAs) recovers fp32 accuracy.
// M=100 padded to 112 (7 m16 tiles), K=20 padded to 24 (3 k8 tiles), N=128.
// R10 crash fix: QSTRIDE must cover the PADDED m rows (112) -> 113.
// Grid coords / beta / W are all read from the input arrays at runtime.
// ---------------------------------------------------------------------------

#define LOG2E 1.4426950408889634f
#define NI 20
#define NJ 5
#define NK 20
#define MROWS 100           // ij rows
#define MPAD  112           // 7 * 16
#define KPAD  24            // 3 * 8
#define ASTRIDE 25          // W smem row stride
#define BSTRIDE 129         // ws smem row stride
#define QSTRIDE 113         // >= MPAD, odd -> conflict-free epilogue reads
#define TILE_N 128
#define TPB 128

__device__ float g_Whi[MPAD * ASTRIDE];
__device__ float g_Wlo[MPAD * ASTRIDE];

__device__ __forceinline__ float ex2f(float x) {
    float r; asm("ex2.approx.ftz.f32 %0, %1;" : "=f"(r) : "f"(x)); return r;
}
__device__ __forceinline__ unsigned f2tf32(float a) {
    unsigned r; asm("cvt.rna.tf32.f32 %0, %1;" : "=r"(r) : "f"(a)); return r;
}
__device__ __forceinline__ void mma_tf32(float c[4], const unsigned a[4], const unsigned b[2]) {
    asm volatile(
        "mma.sync.aligned.m16n8k8.row.col.f32.tf32.tf32.f32 "
        "{%0,%1,%2,%3}, {%4,%5,%6,%7}, {%8,%9}, {%0,%1,%2,%3};"
        : "+f"(c[0]), "+f"(c[1]), "+f"(c[2]), "+f"(c[3])
        : "r"(a[0]), "r"(a[1]), "r"(a[2]), "r"(a[3]), "r"(b[0]), "r"(b[1]));
}

__global__ void precompute_kernel(const float* __restrict__ lin_w) {
    int idx = blockIdx.x * blockDim.x + threadIdx.x;
    if (idx >= MPAD * ASTRIDE) return;
    int m = idx / ASTRIDE, k = idx % ASTRIDE;
    float v = 0.f;
    if (m < MROWS && k < NK) {
        int i = m / NJ, j = m % NJ;
        v = lin_w[i * (NJ * NK) + j * NK + k];
    }
    unsigned hi = f2tf32(v);
    float fhi = __uint_as_float(hi);
    g_Whi[idx] = fhi;
    g_Wlo[idx] = __uint_as_float(f2tf32(v - fhi));
}

__global__ __launch_bounds__(TPB)
void rbf_tc_kernel(const float* __restrict__ x,
                   const float* __restrict__ centers,
                   const float* __restrict__ beta,
                   float* __restrict__ out, int N) {
    extern __shared__ float smem[];
    float* Whi_s = smem;                               // MPAD*ASTRIDE = 2800
    float* Wlo_s = Whi_s + MPAD * ASTRIDE;             // 2800
    float* wsh   = Wlo_s + MPAD * ASTRIDE;             // KPAD*BSTRIDE = 3096
    float* wsl   = wsh + KPAD * BSTRIDE;               // 3096
    float* Qs    = wsl + KPAD * BSTRIDE;               // TILE_N*QSTRIDE = 14464

    __shared__ float sg1[NI], sg2[NJ], sg3[NK];

    int tid = threadIdx.x;
    int lane = tid & 31, warp = tid >> 5;

    // stage W (already split) and grid coords
    for (int i = tid; i < MPAD * ASTRIDE; i += TPB) {
        Whi_s[i] = g_Whi[i];
        Wlo_s[i] = g_Wlo[i];
    }
    if (tid < NI) sg1[tid] = centers[3 * (tid * (NJ * NK)) + 0];
    if (tid < NJ) sg2[tid] = centers[3 * (tid * NK) + 1];
    if (tid < NK) sg3[tid] = centers[3 * tid + 2];
    __syncthreads();

    int gidx = blockIdx.x * TILE_N + tid;              // this thread's point
    float nbl = -beta[0] * LOG2E;

    float x0 = 0.f, x1 = 0.f, x2 = 0.f;
    if (gidx < N) { x0 = x[3 * gidx]; x1 = x[3 * gidx + 1]; x2 = x[3 * gidx + 2]; }

    // ---- prologue: per-point 1D Gaussians ----
    float U[NI], V[NJ];
    float sumu = 0.f, sumv = 0.f, sumw = 0.f;
    #pragma unroll
    for (int k = 0; k < NK; ++k) {
        float d = x2 - sg3[k];
        float wk = ex2f(nbl * d * d);
        sumw += wk;
        unsigned hi = f2tf32(wk);
        float fhi = __uint_as_float(hi);
        wsh[k * BSTRIDE + tid] = fhi;
        wsl[k * BSTRIDE + tid] = __uint_as_float(f2tf32(wk - fhi));
    }
    #pragma unroll
    for (int k = NK; k < KPAD; ++k) {   // zero K padding
        wsh[k * BSTRIDE + tid] = 0.f;
        wsl[k * BSTRIDE + tid] = 0.f;
    }
    #pragma unroll
    for (int j = 0; j < NJ; ++j) {
        float d = x1 - sg2[j];
        V[j] = ex2f(nbl * d * d);
        sumv += V[j];
    }
    #pragma unroll
    for (int i = 0; i < NI; ++i) {
        float d = x0 - sg1[i];
        U[i] = ex2f(nbl * d * d);
        sumu += U[i];
    }
    float den = sumu * sumv * sumw;
    __syncthreads();

    // ---- GEMM: Q[112 x 128] = W[112 x 24] * ws[24 x 128], 3xTF32 ----
    for (int mt = 0; mt < MPAD / 16; ++mt) {
        unsigned Ah[3][4], Al[3][4];
        int ar = mt * 16 + (lane >> 2);
        int ac = lane & 3;
        #pragma unroll
        for (int kt = 0; kt < 3; ++kt) {
            int kc = kt * 8 + ac;
            Ah[kt][0] = __float_as_uint(Whi_s[ar * ASTRIDE + kc]);
            Ah[kt][1] = __float_as_uint(Whi_s[(ar + 8) * ASTRIDE + kc]);
            Ah[kt][2] = __float_as_uint(Whi_s[ar * ASTRIDE + kc + 4]);
            Ah[kt][3] = __float_as_uint(Whi_s[(ar + 8) * ASTRIDE + kc + 4]);
            Al[kt][0] = __float_as_uint(Wlo_s[ar * ASTRIDE + kc]);
            Al[kt][1] = __float_as_uint(Wlo_s[(ar + 8) * ASTRIDE + kc]);
            Al[kt][2] = __float_as_uint(Wlo_s[ar * ASTRIDE + kc + 4]);
            Al[kt][3] = __float_as_uint(Wlo_s[(ar + 8) * ASTRIDE + kc + 4]);
        }
        #pragma unroll
        for (int t = 0; t < 4; ++t) {
            int nt = warp * 4 + t;
            int nb = nt * 8 + (lane >> 2);
            int kb = lane & 3;
            float c[4] = {0.f, 0.f, 0.f, 0.f};
            #pragma unroll
            for (int kt = 0; kt < 3; ++kt) {
                unsigned bh[2], bl[2];
                bh[0] = __float_as_uint(wsh[(kt * 8 + kb) * BSTRIDE + nb]);
                bh[1] = __float_as_uint(wsh[(kt * 8 + kb + 4) * BSTRIDE + nb]);
                bl[0] = __float_as_uint(wsl[(kt * 8 + kb) * BSTRIDE + nb]);
                bl[1] = __float_as_uint(wsl[(kt * 8 + kb + 4) * BSTRIDE + nb]);
                mma_tf32(c, Ah[kt], bh);
                mma_tf32(c, Ah[kt], bl);
                mma_tf32(c, Al[kt], bh);
            }
            int r0 = mt * 16 + (lane >> 2);
            int cc = nt * 8 + 2 * (lane & 3);
            Qs[cc * QSTRIDE + r0]           = c[0];
            Qs[(cc + 1) * QSTRIDE + r0]     = c[1];
            Qs[cc * QSTRIDE + r0 + 8]       = c[2];
            Qs[(cc + 1) * QSTRIDE + r0 + 8] = c[3];
        }
    }
    __syncthreads();

    // ---- epilogue: num = sum_i U_i sum_j V_j Q[i*5+j, tid] ----
    if (gidx < N) {
        const float* q = &Qs[tid * QSTRIDE];
        float num = 0.f;
        #pragma unroll
        for (int i = 0; i < NI; ++i) {
            float ti = 0.f;
            #pragma unroll
            for (int j = 0; j < NJ; ++j)
                ti = fmaf(V[j], q[i * NJ + j], ti);
            num = fmaf(U[i], ti, num);
        }
        out[gidx] = __fdividef(num, den);
    }
}

extern "C" void kernel_launch(void* const* d_in, const int* in_sizes, int n_in,
                              void* d_out, int out_size) {
    const float* x       = (const float*)d_in[0];
    const float* centers = (const float*)d_in[1];
    const float* beta    = (const float*)d_in[2];
    const float* lin_w   = (const float*)d_in[3];
    float* out = (float*)d_out;

    int N = in_sizes[0] / 3;                         // 131072

    int smem_bytes = (2 * MPAD * ASTRIDE + 2 * KPAD * BSTRIDE + TILE_N * QSTRIDE)
                     * (int)sizeof(float);           // ~102.6 KB
    cudaFuncSetAttribute(rbf_tc_kernel,
                         cudaFuncAttributeMaxDynamicSharedMemorySize, smem_bytes);

    precompute_kernel<<<(MPAD * ASTRIDE + 255) / 256, 256>>>(lin_w);

    int nblocks = (N + TILE_N - 1) / TILE_N;         // 1024
    rbf_tc_kernel<<<nblocks, TPB, smem_bytes>>>(x, centers, beta, out, N);
}

// round 12
// speedup vs baseline: 1.4830x; 1.4830x over previous
#include <cuda_runtime.h>
#include <cuda_bf16.h>

// ---------------------------------------------------------------------------
// Separable RBF network (centers = 20x5x20 meshgrid, uniform beta):
//   exp(-beta|x-c|^2) = u_i(x0) * v_j(x1) * w_k(x2)
//   out = ( sum_ijk W[i,j,k] u_i v_j w_k ) / ( (sum u)(sum v)(sum w) )
// Tensor-core formulation, v2:
//   Q[ij, n] = sum_k Wmat[ij, k] * w_k(n)     (mma.sync m16n8k8 tf32, 3x split)
//   num(n)   = sum_i U_i(n) sum_j V_j(n) Q[i*5+j, n]
// v2 operand delivery:
//   - A (W) fragments loaded ONCE per warp into registers from global
//   - warps own m-tiles (2/2/2/1); nt outer loop so each B fragment is
//     loaded once and reused across the warp's m-tiles
//   - Q stored row-major with STS.64; epilogue reads are lane-consecutive
// ---------------------------------------------------------------------------

#define LOG2E 1.4426950408889634f
#define NI 20
#define NJ 5
#define NK 20
#define MROWS 100
#define MPAD  112           // 7 * 16
#define KPAD  24            // 3 * 8
#define ASTRIDE 25          // g_W row stride
#define BSTRIDE 129         // ws smem row stride
#define QSTRIDE 130         // Q row-major row stride (even: STS.64-aligned)
#define TILE_N 128
#define TPB 128

__device__ float g_Whi[MPAD * ASTRIDE];
__device__ float g_Wlo[MPAD * ASTRIDE];

__device__ __forceinline__ float ex2f(float x) {
    float r; asm("ex2.approx.ftz.f32 %0, %1;" : "=f"(r) : "f"(x)); return r;
}
__device__ __forceinline__ unsigned f2tf32(float a) {
    unsigned r; asm("cvt.rna.tf32.f32 %0, %1;" : "=r"(r) : "f"(a)); return r;
}
__device__ __forceinline__ void mma_tf32(float c[4], const unsigned a[4], const unsigned b[2]) {
    asm volatile(
        "mma.sync.aligned.m16n8k8.row.col.f32.tf32.tf32.f32 "
        "{%0,%1,%2,%3}, {%4,%5,%6,%7}, {%8,%9}, {%0,%1,%2,%3};"
        : "+f"(c[0]), "+f"(c[1]), "+f"(c[2]), "+f"(c[3])
        : "r"(a[0]), "r"(a[1]), "r"(a[2]), "r"(a[3]), "r"(b[0]), "r"(b[1]));
}

__global__ void precompute_kernel(const float* __restrict__ lin_w) {
    int idx = blockIdx.x * blockDim.x + threadIdx.x;
    if (idx >= MPAD * ASTRIDE) return;
    int m = idx / ASTRIDE, k = idx % ASTRIDE;
    float v = 0.f;
    if (m < MROWS && k < NK) {
        int i = m / NJ, j = m % NJ;
        v = lin_w[i * (NJ * NK) + j * NK + k];
    }
    unsigned hi = f2tf32(v);
    float fhi = __uint_as_float(hi);
    g_Whi[idx] = fhi;
    g_Wlo[idx] = __uint_as_float(f2tf32(v - fhi));
}

__global__ __launch_bounds__(TPB)
void rbf_tc_kernel(const float* __restrict__ x,
                   const float* __restrict__ centers,
                   const float* __restrict__ beta,
                   float* __restrict__ out, int N) {
    extern __shared__ float smem[];
    float* wsh = smem;                         // KPAD*BSTRIDE = 3096
    float* wsl = wsh + KPAD * BSTRIDE;         // 3096
    float* Qs  = wsl + KPAD * BSTRIDE;         // MPAD*QSTRIDE = 14560 (row-major)

    __shared__ float sg1[NI], sg2[NJ], sg3[NK];

    int tid = threadIdx.x;
    int lane = tid & 31, warp = tid >> 5;

    if (tid < NI) sg1[tid] = centers[3 * (tid * (NJ * NK)) + 0];
    if (tid < NJ) sg2[tid] = centers[3 * (tid * NK) + 1];
    if (tid < NK) sg3[tid] = centers[3 * tid + 2];

    // ---- A fragments: once per warp, straight from global to registers ----
    // warp w owns m-tiles {2w, 2w+1} (w<3) or {6} (w==3)
    int nmt = (warp < 3) ? 2 : 1;
    int mt0 = (warp < 3) ? 2 * warp : 6;
    unsigned Ah[2][3][4], Al[2][3][4];
    #pragma unroll
    for (int mi = 0; mi < 2; ++mi) {
        if (mi >= nmt) break;
        int ar = (mt0 + mi) * 16 + (lane >> 2);
        int ac = lane & 3;
        #pragma unroll
        for (int kt = 0; kt < 3; ++kt) {
            int kc = kt * 8 + ac;
            Ah[mi][kt][0] = __float_as_uint(g_Whi[ar * ASTRIDE + kc]);
            Ah[mi][kt][1] = __float_as_uint(g_Whi[(ar + 8) * ASTRIDE + kc]);
            Ah[mi][kt][2] = __float_as_uint(g_Whi[ar * ASTRIDE + kc + 4]);
            Ah[mi][kt][3] = __float_as_uint(g_Whi[(ar + 8) * ASTRIDE + kc + 4]);
            Al[mi][kt][0] = __float_as_uint(g_Wlo[ar * ASTRIDE + kc]);
            Al[mi][kt][1] = __float_as_uint(g_Wlo[(ar + 8) * ASTRIDE + kc]);
            Al[mi][kt][2] = __float_as_uint(g_Wlo[ar * ASTRIDE + kc + 4]);
            Al[mi][kt][3] = __float_as_uint(g_Wlo[(ar + 8) * ASTRIDE + kc + 4]);
        }
    }
    __syncthreads();

    int gidx = blockIdx.x * TILE_N + tid;      // this thread's point
    float nbl = -beta[0] * LOG2E;

    float x0 = 0.f, x1 = 0.f, x2 = 0.f;
    if (gidx < N) { x0 = x[3 * gidx]; x1 = x[3 * gidx + 1]; x2 = x[3 * gidx + 2]; }

    // ---- prologue: per-point 1D Gaussians; w -> smem split hi/lo ----
    float U[NI], V[NJ];
    float sumu = 0.f, sumv = 0.f, sumw = 0.f;
    #pragma unroll
    for (int k = 0; k < NK; ++k) {
        float d = x2 - sg3[k];
        float wk = ex2f(nbl * d * d);
        sumw += wk;
        unsigned hi = f2tf32(wk);
        float fhi = __uint_as_float(hi);
        wsh[k * BSTRIDE + tid] = fhi;
        wsl[k * BSTRIDE + tid] = __uint_as_float(f2tf32(wk - fhi));
    }
    #pragma unroll
    for (int k = NK; k < KPAD; ++k) {          // zero K padding
        wsh[k * BSTRIDE + tid] = 0.f;
        wsl[k * BSTRIDE + tid] = 0.f;
    }
    #pragma unroll
    for (int j = 0; j < NJ; ++j) {
        float d = x1 - sg2[j];
        V[j] = ex2f(nbl * d * d);
        sumv += V[j];
    }
    #pragma unroll
    for (int i = 0; i < NI; ++i) {
        float d = x0 - sg1[i];
        U[i] = ex2f(nbl * d * d);
        sumu += U[i];
    }
    float den = sumu * sumv * sumw;
    __syncthreads();

    // ---- GEMM: Q[112 x 128] = W[112 x 24] * ws[24 x 128], 3xTF32 ----
    int kb = lane & 3;
    int nbase = lane >> 2;
    for (int nt = 0; nt < TILE_N / 8; ++nt) {
        int nb = nt * 8 + nbase;
        unsigned bh[3][2], bl[3][2];
        #pragma unroll
        for (int kt = 0; kt < 3; ++kt) {       // B loaded once, reused across mts
            bh[kt][0] = __float_as_uint(wsh[(kt * 8 + kb) * BSTRIDE + nb]);
            bh[kt][1] = __float_as_uint(wsh[(kt * 8 + kb + 4) * BSTRIDE + nb]);
            bl[kt][0] = __float_as_uint(wsl[(kt * 8 + kb) * BSTRIDE + nb]);
            bl[kt][1] = __float_as_uint(wsl[(kt * 8 + kb + 4) * BSTRIDE + nb]);
        }
        #pragma unroll
        for (int mi = 0; mi < 2; ++mi) {
            if (mi >= nmt) break;
            float c[4] = {0.f, 0.f, 0.f, 0.f};
            #pragma unroll
            for (int kt = 0; kt < 3; ++kt) {
                mma_tf32(c, Ah[mi][kt], bh[kt]);
                mma_tf32(c, Ah[mi][kt], bl[kt]);
                mma_tf32(c, Al[mi][kt], bh[kt]);
            }
            // row-major Q: (c0,c1) and (c2,c3) are col-adjacent -> STS.64
            int r0 = (mt0 + mi) * 16 + (lane >> 2);
            int cc = nt * 8 + 2 * (lane & 3);
            *reinterpret_cast<float2*>(&Qs[r0 * QSTRIDE + cc])       = make_float2(c[0], c[1]);
            *reinterpret_cast<float2*>(&Qs[(r0 + 8) * QSTRIDE + cc]) = make_float2(c[2], c[3]);
        }
    }
    __syncthreads();

    // ---- epilogue: num = sum_i U_i sum_j V_j Q[i*5+j][tid] ----
    if (gidx < N) {
        float num = 0.f;
        #pragma unroll
        for (int i = 0; i < NI; ++i) {
            float ti = 0.f;
            #pragma unroll
            for (int j = 0; j < NJ; ++j)
                ti = fmaf(V[j], Qs[(i * NJ + j) * QSTRIDE + tid], ti);
            num = fmaf(U[i], ti, num);
        }
        out[gidx] = __fdividef(num, den);
    }
}

extern "C" void kernel_launch(void* const* d_in, const int* in_sizes, int n_in,
                              void* d_out, int out_size) {
    const float* x       = (const float*)d_in[0];
    const float* centers = (const float*)d_in[1];
    const float* beta    = (const float*)d_in[2];
    const float* lin_w   = (const float*)d_in[3];
    float* out = (float*)d_out;

    int N = in_sizes[0] / 3;                         // 131072

    int smem_bytes = (2 * KPAD * BSTRIDE + MPAD * QSTRIDE) * (int)sizeof(float); // ~83 KB
    cudaFuncSetAttribute(rbf_tc_kernel,
                         cudaFuncAttributeMaxDynamicSharedMemorySize, smem_bytes);

    precompute_kernel<<<(MPAD * ASTRIDE + 255) / 256, 256>>>(lin_w);

    int nblocks = (N + TILE_N - 1) / TILE_N;         // 1024
    rbf_tc_kernel<<<nblocks, TPB, smem_bytes>>>(x, centers, beta, out, N);
}

// round 15
// speedup vs baseline: 2.4222x; 1.6333x over previous
#include <cuda_runtime.h>
#include <cuda_bf16.h>

// ---------------------------------------------------------------------------
// Separable RBF network (centers = 20x5x20 meshgrid, uniform beta):
//   exp(-beta|x-c|^2) = u_i(x0) * v_j(x1) * w_k(x2)
//   out = ( sum_ijk W[i,j,k] u_i v_j w_k ) / ( (sum u)(sum v)(sum w) )
// ONE point per thread, f32x2 lanes pack two adjacent k-indices.
// KEY CHANGE vs R9: W lives in __constant__ memory (copied in via
// cudaMemcpyToSymbolAsync, D2D, graph-capturable). W reads are warp-uniform
// compile-time offsets -> constant port (LDCU/LDC), completely off the
// L1/LDS pipe that bound every previous variant. lin_w's natural layout
// (c = i*100 + j*20 + k) is exactly the (W_k,W_k+1) pairing fma2 needs.
// ---------------------------------------------------------------------------

#define LOG2E 1.4426950408889634f
#define NI 20
#define NJ 5
#define NK 20
#define NC (NI*NJ*NK)
#define TPB 128

typedef unsigned long long u64;

__constant__ __align__(16) float cW[NC];   // 8 KB

__device__ __forceinline__ u64 pk2(float lo, float hi) {
    u64 r; asm("mov.b64 %0, {%1, %2};" : "=l"(r) : "f"(lo), "f"(hi)); return r;
}
__device__ __forceinline__ void upk2(u64 v, float &lo, float &hi) {
    asm("mov.b64 {%0, %1}, %2;" : "=f"(lo), "=f"(hi) : "l"(v));
}
__device__ __forceinline__ u64 fma2(u64 a, u64 b, u64 c) {
    u64 d; asm("fma.rn.f32x2 %0, %1, %2, %3;" : "=l"(d) : "l"(a), "l"(b), "l"(c)); return d;
}
__device__ __forceinline__ u64 add2(u64 a, u64 b) {
    u64 d; asm("add.rn.f32x2 %0, %1, %2;" : "=l"(d) : "l"(a), "l"(b)); return d;
}
__device__ __forceinline__ float ex2f(float x) {
    float r; asm("ex2.approx.ftz.f32 %0, %1;" : "=f"(r) : "f"(x)); return r;
}

__global__ __launch_bounds__(TPB)
void rbf_sep_kernel(const float* __restrict__ x,
                    const float* __restrict__ centers,
                    const float* __restrict__ beta,
                    float* __restrict__ out, int N) {
    __shared__ float sg1[NI], sg2[NJ], sg3[NK];

    if (threadIdx.x < NI) sg1[threadIdx.x] = centers[3 * (threadIdx.x * (NJ * NK)) + 0];
    if (threadIdx.x < NJ) sg2[threadIdx.x] = centers[3 * (threadIdx.x * NK) + 1];
    if (threadIdx.x < NK) sg3[threadIdx.x] = centers[3 * threadIdx.x + 2];
    __syncthreads();

    int t = blockIdx.x * TPB + threadIdx.x;    // one point per thread
    if (t >= N) return;

    float nbl = -beta[0] * LOG2E;              // -beta * log2(e)

    float x0 = x[3 * t + 0];
    float x1 = x[3 * t + 1];
    float x2 = x[3 * t + 2];

    // k-dim Gaussians as (k, k+1) register pairs
    u64 wv[NK / 2];
    float sumw = 0.f;
    #pragma unroll
    for (int k = 0; k < NK; k += 2) {
        float d0 = x2 - sg3[k], d1 = x2 - sg3[k + 1];
        float e0 = ex2f(nbl * d0 * d0), e1 = ex2f(nbl * d1 * d1);
        sumw += e0 + e1;
        wv[k / 2] = pk2(e0, e1);
    }

    // j-dim Gaussians, duplicated pairs
    u64 V[NJ];
    float sumv = 0.f;
    #pragma unroll
    for (int j = 0; j < NJ; ++j) {
        float d = x1 - sg2[j];
        float v = ex2f(nbl * d * d);
        sumv += v;
        V[j] = pk2(v, v);
    }

    float svw = sumv * sumw;

    u64 num = 0ull;
    float sumu = 0.f;

    #pragma unroll 4
    for (int i = 0; i < NI; ++i) {
        float d = x0 - sg1[i];
        float u = ex2f(nbl * d * d);
        sumu += u;
        u64 U = pk2(u, u);

        u64 ta = 0ull;
        #pragma unroll
        for (int j = 0; j < NJ; ++j) {
            // W from __constant__: warp-uniform, compile-time offsets
            const ulonglong2* Wp =
                reinterpret_cast<const ulonglong2*>(cW + i * (NJ * NK) + j * NK);
            u64 k0 = 0ull, k1 = 0ull;
            #pragma unroll
            for (int q = 0; q < NK / 4; ++q) {
                ulonglong2 wq = Wp[q];                // (W,W') , (W'',W''')
                k0 = fma2(wq.x, wv[2 * q + 0], k0);
                k1 = fma2(wq.y, wv[2 * q + 1], k1);
            }
            ta = fma2(V[j], add2(k0, k1), ta);
        }
        num = fma2(U, ta, num);
    }

    float nlo, nhi;
    upk2(num, nlo, nhi);
    out[t] = __fdividef(nlo + nhi, sumu * svw);
}

extern "C" void kernel_launch(void* const* d_in, const int* in_sizes, int n_in,
                              void* d_out, int out_size) {
    const float* x       = (const float*)d_in[0];
    const float* centers = (const float*)d_in[1];
    const float* beta    = (const float*)d_in[2];
    const float* lin_w   = (const float*)d_in[3];
    float* out = (float*)d_out;

    int N = in_sizes[0] / 3;                    // 131072

    // Stage W into constant memory (device-to-device, graph-capturable)
    cudaMemcpyToSymbolAsync(cW, lin_w, NC * sizeof(float), 0,
                            cudaMemcpyDeviceToDevice);

    int nblocks = (N + TPB - 1) / TPB;          // 1024
    rbf_sep_kernel<<<nblocks, TPB>>>(x, centers, beta, out, N);
}

// round 16
// speedup vs baseline: 2.4256x; 1.0014x over previous
#include <cuda_runtime.h>
#include <cuda_bf16.h>

// ---------------------------------------------------------------------------
// Separable RBF network (centers = 20x5x20 meshgrid, uniform beta):
//   exp(-beta|x-c|^2) = u_i(x0) * v_j(x1) * w_k(x2)
//   out = ( sum_ijk W[i,j,k] u_i v_j w_k ) / ( (sum u)(sum v)(sum w) )
// ONE point per thread, f32x2 lanes pack two adjacent k-indices.
// W delivery is split across BOTH operand ports to avoid either's floor:
//   j == 0    -> __constant__ cW   (constant port, rt floor 8)
//   j in 1..4 -> shared sW         (LDS crossbar broadcast, rt floor 2)
// Port time ~5.5K cyc each per SMSP @ 6.9 warps, both under the fma floor.
// ---------------------------------------------------------------------------

#define LOG2E 1.4426950408889634f
#define NI 20
#define NJ 5
#define NK 20
#define NC (NI*NJ*NK)
#define TPB 128

typedef unsigned long long u64;

__constant__ __align__(16) float cW[NC];   // 8 KB staged copy of lin_w

__device__ __forceinline__ u64 pk2(float lo, float hi) {
    u64 r; asm("mov.b64 %0, {%1, %2};" : "=l"(r) : "f"(lo), "f"(hi)); return r;
}
__device__ __forceinline__ void upk2(u64 v, float &lo, float &hi) {
    asm("mov.b64 {%0, %1}, %2;" : "=f"(lo), "=f"(hi) : "l"(v));
}
__device__ __forceinline__ u64 fma2(u64 a, u64 b, u64 c) {
    u64 d; asm("fma.rn.f32x2 %0, %1, %2, %3;" : "=l"(d) : "l"(a), "l"(b), "l"(c)); return d;
}
__device__ __forceinline__ u64 add2(u64 a, u64 b) {
    u64 d; asm("add.rn.f32x2 %0, %1, %2;" : "=l"(d) : "l"(a), "l"(b)); return d;
}
__device__ __forceinline__ float ex2f(float x) {
    float r; asm("ex2.approx.ftz.f32 %0, %1;" : "=f"(r) : "f"(x)); return r;
}

__global__ __launch_bounds__(TPB)
void rbf_sep_kernel(const float* __restrict__ x,
                    const float* __restrict__ centers,
                    const float* __restrict__ beta,
                    const float* __restrict__ lin_w,
                    float* __restrict__ out, int N) {
    // smem copy of W for the j>=1 portion (LDS broadcast path)
    __shared__ __align__(16) float sW[NC];
    __shared__ float sg1[NI], sg2[NJ], sg3[NK];

    for (int c = threadIdx.x; c < NC; c += TPB) sW[c] = lin_w[c];
    if (threadIdx.x < NI) sg1[threadIdx.x] = centers[3 * (threadIdx.x * (NJ * NK)) + 0];
    if (threadIdx.x < NJ) sg2[threadIdx.x] = centers[3 * (threadIdx.x * NK) + 1];
    if (threadIdx.x < NK) sg3[threadIdx.x] = centers[3 * threadIdx.x + 2];
    __syncthreads();

    int t = blockIdx.x * TPB + threadIdx.x;    // one point per thread
    if (t >= N) return;

    float nbl = -beta[0] * LOG2E;              // -beta * log2(e)

    float x0 = x[3 * t + 0];
    float x1 = x[3 * t + 1];
    float x2 = x[3 * t + 2];

    // k-dim Gaussians as (k, k+1) register pairs
    u64 wv[NK / 2];
    float sumw = 0.f;
    #pragma unroll
    for (int k = 0; k < NK; k += 2) {
        float d0 = x2 - sg3[k], d1 = x2 - sg3[k + 1];
        float e0 = ex2f(nbl * d0 * d0), e1 = ex2f(nbl * d1 * d1);
        sumw += e0 + e1;
        wv[k / 2] = pk2(e0, e1);
    }

    // j-dim Gaussians, duplicated pairs
    u64 V[NJ];
    float sumv = 0.f;
    #pragma unroll
    for (int j = 0; j < NJ; ++j) {
        float d = x1 - sg2[j];
        float v = ex2f(nbl * d * d);
        sumv += v;
        V[j] = pk2(v, v);
    }

    float svw = sumv * sumw;

    u64 num = 0ull;
    float sumu = 0.f;

    #pragma unroll 4
    for (int i = 0; i < NI; ++i) {
        float d = x0 - sg1[i];
        float u = ex2f(nbl * d * d);
        sumu += u;
        u64 U = pk2(u, u);

        u64 ta = 0ull;

        // ---- j = 0: W from the CONSTANT port ----
        {
            const ulonglong2* Wp =
                reinterpret_cast<const ulonglong2*>(cW + i * (NJ * NK));
            u64 k0 = 0ull, k1 = 0ull;
            #pragma unroll
            for (int q = 0; q < NK / 4; ++q) {
                ulonglong2 wq = Wp[q];                // LDC.128
                k0 = fma2(wq.x, wv[2 * q + 0], k0);
                k1 = fma2(wq.y, wv[2 * q + 1], k1);
            }
            ta = fma2(V[0], add2(k0, k1), ta);
        }

        // ---- j = 1..4: W from SHARED (broadcast LDS) ----
        #pragma unroll
        for (int j = 1; j < NJ; ++j) {
            const ulonglong2* Wp =
                reinterpret_cast<const ulonglong2*>(sW + i * (NJ * NK) + j * NK);
            u64 k0 = 0ull, k1 = 0ull;
            #pragma unroll
            for (int q = 0; q < NK / 4; ++q) {
                ulonglong2 wq = Wp[q];                // LDS.128 broadcast
                k0 = fma2(wq.x, wv[2 * q + 0], k0);
                k1 = fma2(wq.y, wv[2 * q + 1], k1);
            }
            ta = fma2(V[j], add2(k0, k1), ta);
        }

        num = fma2(U, ta, num);
    }

    float nlo, nhi;
    upk2(num, nlo, nhi);
    out[t] = __fdividef(nlo + nhi, sumu * svw);
}

extern "C" void kernel_launch(void* const* d_in, const int* in_sizes, int n_in,
                              void* d_out, int out_size) {
    const float* x       = (const float*)d_in[0];
    const float* centers = (const float*)d_in[1];
    const float* beta    = (const float*)d_in[2];
    const float* lin_w   = (const float*)d_in[3];
    float* out = (float*)d_out;

    int N = in_sizes[0] / 3;                    // 131072

    // Stage W into constant memory (device-to-device, graph-capturable)
    cudaMemcpyToSymbolAsync(cW, lin_w, NC * sizeof(float), 0,
                            cudaMemcpyDeviceToDevice);

    int nblocks = (N + TPB - 1) / TPB;          // 1024
    rbf_sep_kernel<<<nblocks, TPB>>>(x, centers, beta, lin_w, out, N);
}

// round 17
// speedup vs baseline: 2.4460x; 1.0084x over previous
#include <cuda_runtime.h>
#include <cuda_bf16.h>

// ---------------------------------------------------------------------------
// Separable RBF network (centers = 20x5x20 meshgrid, uniform beta):
//   exp(-beta|x-c|^2) = u_i(x0) * v_j(x1) * w_k(x2)
//   out = ( sum_ijk W[i,j,k] u_i v_j w_k ) / ( (sum u)(sum v)(sum w) )
// TWO points per thread, f32x2 lanes pack two adjacent k-indices of one
// point. W comes EXCLUSIVELY from __constant__ memory (LDC.128, warp-uniform
// compile-time offsets): R15 proved this leaves the L1 pipe empty (2%), and
// halving thread count halves the constant-port traffic that bound R15.
// Each LDC.128 now feeds 4 fma2 (2 points x 2 chains) -> fma-pipe-bound.
// ---------------------------------------------------------------------------

#define LOG2E 1.4426950408889634f
#define NI 20
#define NJ 5
#define NK 20
#define NC (NI*NJ*NK)
#define TPB 64
#define PPT 2

typedef unsigned long long u64;

__constant__ __align__(16) float cW[NC];   // 8 KB staged copy of lin_w

__device__ __forceinline__ u64 pk2(float lo, float hi) {
    u64 r; asm("mov.b64 %0, {%1, %2};" : "=l"(r) : "f"(lo), "f"(hi)); return r;
}
__device__ __forceinline__ void upk2(u64 v, float &lo, float &hi) {
    asm("mov.b64 {%0, %1}, %2;" : "=f"(lo), "=f"(hi) : "l"(v));
}
__device__ __forceinline__ u64 fma2(u64 a, u64 b, u64 c) {
    u64 d; asm("fma.rn.f32x2 %0, %1, %2, %3;" : "=l"(d) : "l"(a), "l"(b), "l"(c)); return d;
}
__device__ __forceinline__ u64 add2(u64 a, u64 b) {
    u64 d; asm("add.rn.f32x2 %0, %1, %2;" : "=l"(d) : "l"(a), "l"(b)); return d;
}
__device__ __forceinline__ float ex2f(float x) {
    float r; asm("ex2.approx.ftz.f32 %0, %1;" : "=f"(r) : "f"(x)); return r;
}

__global__ __launch_bounds__(TPB)
void rbf_sep_kernel(const float* __restrict__ x,
                    const float* __restrict__ centers,
                    const float* __restrict__ beta,
                    float* __restrict__ out, int N) {
    __shared__ float sg1[NI], sg2[NJ], sg3[NK];

    if (threadIdx.x < NI) sg1[threadIdx.x] = centers[3 * (threadIdx.x * (NJ * NK)) + 0];
    if (threadIdx.x < NJ) sg2[threadIdx.x] = centers[3 * (threadIdx.x * NK) + 1];
    if (threadIdx.x < NK) sg3[threadIdx.x] = centers[3 * threadIdx.x + 2];
    __syncthreads();

    int t = blockIdx.x * TPB + threadIdx.x;    // 2-point group index
    int p0 = PPT * t;
    if (p0 + 1 >= N) return;                   // N even

    float nbl = -beta[0] * LOG2E;              // -beta * log2(e)

    // 2 points = 6 floats = 3 x float2 (8B aligned)
    const float2* xv = reinterpret_cast<const float2*>(x + 3 * p0);
    float2 f0 = xv[0], f1 = xv[1], f2 = xv[2];
    float X0[PPT] = { f0.x, f1.y };
    float X1[PPT] = { f0.y, f2.x };
    float X2[PPT] = { f1.x, f2.y };

    // k-dim Gaussians as (k, k+1) register pairs, per point
    u64 wv[PPT][NK / 2];
    float sumw[PPT] = {0.f, 0.f};
    #pragma unroll
    for (int k = 0; k < NK; k += 2) {
        float g0 = sg3[k], g1 = sg3[k + 1];
        #pragma unroll
        for (int p = 0; p < PPT; ++p) {
            float d0 = X2[p] - g0, d1 = X2[p] - g1;
            float e0 = ex2f(nbl * d0 * d0), e1 = ex2f(nbl * d1 * d1);
            sumw[p] += e0 + e1;
            wv[p][k / 2] = pk2(e0, e1);
        }
    }

    // j-dim Gaussians, duplicated pairs per point
    u64 V[PPT][NJ];
    float sumv[PPT] = {0.f, 0.f};
    #pragma unroll
    for (int j = 0; j < NJ; ++j) {
        float g = sg2[j];
        #pragma unroll
        for (int p = 0; p < PPT; ++p) {
            float d = X1[p] - g;
            float v = ex2f(nbl * d * d);
            sumv[p] += v;
            V[p][j] = pk2(v, v);
        }
    }

    float svw[PPT];
    #pragma unroll
    for (int p = 0; p < PPT; ++p) svw[p] = sumv[p] * sumw[p];

    u64 num[PPT] = {0ull, 0ull};
    float sumu[PPT] = {0.f, 0.f};

    #pragma unroll 4
    for (int i = 0; i < NI; ++i) {
        float gi = sg1[i];
        u64 U[PPT];
        #pragma unroll
        for (int p = 0; p < PPT; ++p) {
            float d = X0[p] - gi;
            float u = ex2f(nbl * d * d);
            sumu[p] += u;
            U[p] = pk2(u, u);
        }

        u64 ta[PPT] = {0ull, 0ull};
        #pragma unroll
        for (int j = 0; j < NJ; ++j) {
            // W from the constant port: warp-uniform compile-time offsets
            const ulonglong2* Wp =
                reinterpret_cast<const ulonglong2*>(cW + i * (NJ * NK) + j * NK);
            u64 k0[PPT] = {0ull, 0ull};
            u64 k1[PPT] = {0ull, 0ull};
            #pragma unroll
            for (int q = 0; q < NK / 4; ++q) {
                ulonglong2 wq = Wp[q];                // LDC.128 -> 4 fma2
                #pragma unroll
                for (int p = 0; p < PPT; ++p) {
                    k0[p] = fma2(wq.x, wv[p][2 * q + 0], k0[p]);
                    k1[p] = fma2(wq.y, wv[p][2 * q + 1], k1[p]);
                }
            }
            #pragma unroll
            for (int p = 0; p < PPT; ++p)
                ta[p] = fma2(V[p][j], add2(k0[p], k1[p]), ta[p]);
        }
        #pragma unroll
        for (int p = 0; p < PPT; ++p)
            num[p] = fma2(U[p], ta[p], num[p]);
    }

    float2 o;
    {
        float nlo, nhi;
        upk2(num[0], nlo, nhi);
        o.x = __fdividef(nlo + nhi, sumu[0] * svw[0]);
        upk2(num[1], nlo, nhi);
        o.y = __fdividef(nlo + nhi, sumu[1] * svw[1]);
    }
    *reinterpret_cast<float2*>(out + p0) = o;
}

extern "C" void kernel_launch(void* const* d_in, const int* in_sizes, int n_in,
                              void* d_out, int out_size) {
    const float* x       = (const float*)d_in[0];
    const float* centers = (const float*)d_in[1];
    const float* beta    = (const float*)d_in[2];
    const float* lin_w   = (const float*)d_in[3];
    float* out = (float*)d_out;

    int N = in_sizes[0] / 3;                    // 131072

    // Stage W into constant memory (device-to-device, graph-capturable)
    cudaMemcpyToSymbolAsync(cW, lin_w, NC * sizeof(float), 0,
                            cudaMemcpyDeviceToDevice);

    int groups = N / PPT;                       // 65536
    int nblocks = (groups + TPB - 1) / TPB;     // 1024
    rbf_sep_kernel<<<nblocks, TPB>>>(x, centers, beta, out, N);
}